// round 2
// baseline (speedup 1.0000x reference)
#include <cuda_runtime.h>
#include <cstdint>

// ---------------------------------------------------------------------------
// SphereViT forward, fp32 baseline.
// B=32, C=3, P=32, GH=8, GW=16, N=128 tokens, DIM=1024, DEPTH=12, H=16, Dh=64
// ---------------------------------------------------------------------------

#define BATCH     32
#define NTOK      128
#define ROWS      4096            // BATCH * NTOK
#define DIMV      1024
#define PATCHDIM  3072
#define NHEADS    16
#define DHEAD     64
#define DEPTH     12
#define LN_EPS    1e-5f

// -------------------- scratch (device globals; no allocs) ------------------
__device__ float g_big[ROWS * PATCHDIM];   // patches, then expand output (disjoint lifetimes)
__device__ float g_qkv[ROWS * PATCHDIM];   // qkv per layer
__device__ float g_x  [ROWS * DIMV];       // residual stream
__device__ float g_h  [ROWS * DIMV];       // LN output
__device__ float g_o  [ROWS * DIMV];       // attention output (flattened heads)
__device__ float g_w  [BATCH * NHEADS * NTOK * NTOK]; // attention scores / probs

// ---------------------------------------------------------------------------
// Patch extraction: img[b,c,256,512] -> Xp[b*128 + h*16+w][c*1024 + p*32 + q]
// ---------------------------------------------------------------------------
__global__ void extract_patches_kernel(const float* __restrict__ img,
                                       float* __restrict__ Xp) {
    int idx = blockIdx.x * 256 + threadIdx.x;          // 0 .. ROWS*PATCHDIM-1
    int col = idx % PATCHDIM;
    int row = idx / PATCHDIM;
    int b = row >> 7;
    int t = row & 127;
    int h = t >> 4;
    int w = t & 15;
    int c = col >> 10;
    int r = col & 1023;
    int p = r >> 5;
    int q = r & 31;
    Xp[idx] = img[(((size_t)b * 3 + c) * 256 + h * 32 + p) * 512 + w * 32 + q];
}

// ---------------------------------------------------------------------------
// Generic SGEMM: C[M,N] = A[M,K] @ B (+bias[N]) (+res[M,N])
//   TB=false: B row-major [K,N].   TB=true: B row-major [N,K] (i.e. A@B^T)
// Tiles: BM=BN=128, BK=16. 256 threads, 8x8 per thread.
// Requires: M%128==0, N%128==0, K%16==0 (all call sites satisfy this).
// ---------------------------------------------------------------------------
template <bool TB>
__global__ __launch_bounds__(256) void gemm_kernel(
    const float* __restrict__ A, const float* __restrict__ B,
    const float* __restrict__ bias, const float* __restrict__ res,
    float* __restrict__ C, int M, int N, int K)
{
    __shared__ float As[16][128];
    __shared__ float Bs[16][128];
    const int tid = threadIdx.x;
    const int ty = tid >> 4, tx = tid & 15;
    const int m0 = blockIdx.y << 7, n0 = blockIdx.x << 7;
    const int rr = tid >> 2, cc = tid & 3;

    float acc[8][8];
#pragma unroll
    for (int i = 0; i < 8; i++)
#pragma unroll
        for (int j = 0; j < 8; j++) acc[i][j] = 0.f;

    for (int k0 = 0; k0 < K; k0 += 16) {
#pragma unroll
        for (int it = 0; it < 2; it++) {
            int row = rr + it * 64;
            float4 a = *(const float4*)(A + (size_t)(m0 + row) * K + k0 + cc * 4);
            As[cc * 4 + 0][row] = a.x;
            As[cc * 4 + 1][row] = a.y;
            As[cc * 4 + 2][row] = a.z;
            As[cc * 4 + 3][row] = a.w;
        }
        if (TB) {
#pragma unroll
            for (int it = 0; it < 2; it++) {
                int row = rr + it * 64;
                float4 bb = *(const float4*)(B + (size_t)(n0 + row) * K + k0 + cc * 4);
                Bs[cc * 4 + 0][row] = bb.x;
                Bs[cc * 4 + 1][row] = bb.y;
                Bs[cc * 4 + 2][row] = bb.z;
                Bs[cc * 4 + 3][row] = bb.w;
            }
        } else {
#pragma unroll
            for (int it = 0; it < 2; it++) {
                int k  = (tid >> 5) + it * 8;
                int c8 = (tid & 31);
                float4 bb = *(const float4*)(B + (size_t)(k0 + k) * N + n0 + c8 * 4);
                *(float4*)(&Bs[k][c8 * 4]) = bb;
            }
        }
        __syncthreads();
#pragma unroll
        for (int kk = 0; kk < 16; kk++) {
            float av[8], bv[8];
            *(float4*)(av)     = *(const float4*)&As[kk][ty * 8];
            *(float4*)(av + 4) = *(const float4*)&As[kk][ty * 8 + 4];
            *(float4*)(bv)     = *(const float4*)&Bs[kk][tx * 8];
            *(float4*)(bv + 4) = *(const float4*)&Bs[kk][tx * 8 + 4];
#pragma unroll
            for (int i = 0; i < 8; i++)
#pragma unroll
                for (int j = 0; j < 8; j++) acc[i][j] += av[i] * bv[j];
        }
        __syncthreads();
    }

    float bvals[8];
    if (bias) {
        *(float4*)(bvals)     = *(const float4*)(bias + n0 + tx * 8);
        *(float4*)(bvals + 4) = *(const float4*)(bias + n0 + tx * 8 + 4);
    } else {
#pragma unroll
        for (int j = 0; j < 8; j++) bvals[j] = 0.f;
    }
#pragma unroll
    for (int i = 0; i < 8; i++) {
        size_t off = (size_t)(m0 + ty * 8 + i) * N + n0 + tx * 8;
        float out[8];
#pragma unroll
        for (int j = 0; j < 8; j++) out[j] = acc[i][j] + bvals[j];
        if (res) {
            float4 r0 = *(const float4*)(res + off);
            float4 r1 = *(const float4*)(res + off + 4);
            out[0] += r0.x; out[1] += r0.y; out[2] += r0.z; out[3] += r0.w;
            out[4] += r1.x; out[5] += r1.y; out[6] += r1.z; out[7] += r1.w;
        }
        *(float4*)(C + off)     = *(float4*)(out);
        *(float4*)(C + off + 4) = *(float4*)(out + 4);
    }
}

// ---------------------------------------------------------------------------
// LayerNorm over last dim D (one block per row, 256 threads). In-place safe.
// ---------------------------------------------------------------------------
__global__ void ln_kernel(const float* __restrict__ x, const float* __restrict__ g,
                          const float* __restrict__ beta, float* __restrict__ y, int D)
{
    size_t base = (size_t)blockIdx.x * D;
    float s = 0.f, ss = 0.f;
    for (int i = threadIdx.x; i < D; i += 256) {
        float v = x[base + i];
        s += v; ss += v * v;
    }
#pragma unroll
    for (int o = 16; o; o >>= 1) {
        s  += __shfl_xor_sync(0xffffffffu, s, o);
        ss += __shfl_xor_sync(0xffffffffu, ss, o);
    }
    __shared__ float sh[2][8];
    int w = threadIdx.x >> 5;
    if ((threadIdx.x & 31) == 0) { sh[0][w] = s; sh[1][w] = ss; }
    __syncthreads();
    if (threadIdx.x < 32) {
        s  = (threadIdx.x < 8) ? sh[0][threadIdx.x] : 0.f;
        ss = (threadIdx.x < 8) ? sh[1][threadIdx.x] : 0.f;
#pragma unroll
        for (int o = 4; o; o >>= 1) {
            s  += __shfl_xor_sync(0xffffffffu, s, o);
            ss += __shfl_xor_sync(0xffffffffu, ss, o);
        }
        if (threadIdx.x == 0) { sh[0][0] = s; sh[1][0] = ss; }
    }
    __syncthreads();
    s = sh[0][0]; ss = sh[1][0];
    float invD = 1.0f / (float)D;
    float mu = s * invD;
    float var = ss * invD - mu * mu;
    float rstd = rsqrtf(var + LN_EPS);
    for (int i = threadIdx.x; i < D; i += 256) {
        float v = x[base + i];
        y[base + i] = (v - mu) * rstd * g[i] + beta[i];
    }
}

// ---------------------------------------------------------------------------
// x[row][d] += sph_pos[row%128] @ pos_w + pos_b
// ---------------------------------------------------------------------------
__global__ void add_pos_kernel(float* __restrict__ x, const float* __restrict__ sph_pos,
                               const float* __restrict__ pos_w, const float* __restrict__ pos_b)
{
    int idx = blockIdx.x * 256 + threadIdx.x;      // ROWS*DIMV
    int d = idx & 1023;
    int row = idx >> 10;
    int i = row & 127;
    x[idx] += sph_pos[i * 2] * pos_w[d] + sph_pos[i * 2 + 1] * pos_w[1024 + d] + pos_b[d];
}

// ---------------------------------------------------------------------------
// W[b,h,i,j] = (q_i . k_j) * scale * (1 + dist[i,j]).  One block per (b,h).
// ---------------------------------------------------------------------------
__global__ __launch_bounds__(256) void qk_kernel(const float* __restrict__ qkv,
                                                 const float* __restrict__ dist,
                                                 float* __restrict__ W)
{
    int b = blockIdx.x >> 4, hh = blockIdx.x & 15;
    const float* qb = qkv + (size_t)b * NTOK * PATCHDIM + hh * DHEAD;
    const float* kb = qb + DIMV;
    __shared__ float Qs[16][128];
    __shared__ float Ks[16][128];
    int tid = threadIdx.x, ty = tid >> 4, tx = tid & 15;
    int rr = tid >> 2, cc = tid & 3;

    float acc[8][8];
#pragma unroll
    for (int i = 0; i < 8; i++)
#pragma unroll
        for (int j = 0; j < 8; j++) acc[i][j] = 0.f;

    for (int kc = 0; kc < DHEAD; kc += 16) {
#pragma unroll
        for (int it = 0; it < 2; it++) {
            int row = rr + it * 64;
            float4 a = *(const float4*)(qb + (size_t)row * PATCHDIM + kc + cc * 4);
            Qs[cc * 4 + 0][row] = a.x; Qs[cc * 4 + 1][row] = a.y;
            Qs[cc * 4 + 2][row] = a.z; Qs[cc * 4 + 3][row] = a.w;
            float4 k4 = *(const float4*)(kb + (size_t)row * PATCHDIM + kc + cc * 4);
            Ks[cc * 4 + 0][row] = k4.x; Ks[cc * 4 + 1][row] = k4.y;
            Ks[cc * 4 + 2][row] = k4.z; Ks[cc * 4 + 3][row] = k4.w;
        }
        __syncthreads();
#pragma unroll
        for (int kk = 0; kk < 16; kk++) {
            float av[8], bv[8];
            *(float4*)(av)     = *(const float4*)&Qs[kk][ty * 8];
            *(float4*)(av + 4) = *(const float4*)&Qs[kk][ty * 8 + 4];
            *(float4*)(bv)     = *(const float4*)&Ks[kk][tx * 8];
            *(float4*)(bv + 4) = *(const float4*)&Ks[kk][tx * 8 + 4];
#pragma unroll
            for (int i = 0; i < 8; i++)
#pragma unroll
                for (int j = 0; j < 8; j++) acc[i][j] += av[i] * bv[j];
        }
        __syncthreads();
    }

    size_t wbase = (size_t)blockIdx.x * (NTOK * NTOK);
    const float scale = 0.125f;   // DHEAD^-0.5
#pragma unroll
    for (int i = 0; i < 8; i++) {
        int irow = ty * 8 + i;
#pragma unroll
        for (int j = 0; j < 8; j++) {
            int jcol = tx * 8 + j;
            W[wbase + irow * 128 + jcol] =
                acc[i][j] * scale * (1.0f + dist[irow * 128 + jcol]);
        }
    }
}

// ---------------------------------------------------------------------------
// Cross-head standardize (mean/std over heads, ddof=1), then softmax over j.
// One block per (b,i), 128 threads (thread = j). In-place on W.
// ---------------------------------------------------------------------------
__global__ __launch_bounds__(128) void std_softmax_kernel(float* __restrict__ W)
{
    int b = blockIdx.x >> 7, i = blockIdx.x & 127;
    int j = threadIdx.x;
    __shared__ float sm[NHEADS][128];

    size_t base = (size_t)b * (NHEADS * NTOK * NTOK) + (size_t)i * 128 + j;
    float vals[NHEADS];
    float s = 0.f;
#pragma unroll
    for (int h = 0; h < NHEADS; h++) {
        float v = W[base + (size_t)h * (NTOK * NTOK)];
        vals[h] = v; s += v;
    }
    float mu = s * (1.0f / 16.0f);
    float d2 = 0.f;
#pragma unroll
    for (int h = 0; h < NHEADS; h++) {
        float d = vals[h] - mu;
        d2 += d * d;
    }
    float inv = rsqrtf(d2 * (1.0f / 15.0f));   // 1/std, ddof=1
#pragma unroll
    for (int h = 0; h < NHEADS; h++) sm[h][j] = (vals[h] - mu) * inv;
    __syncthreads();

    int warp = j >> 5, lane = j & 31;
#pragma unroll
    for (int r = 0; r < 4; r++) {
        int h = warp * 4 + r;
        float v0 = sm[h][lane], v1 = sm[h][lane + 32];
        float v2 = sm[h][lane + 64], v3 = sm[h][lane + 96];
        float m = fmaxf(fmaxf(v0, v1), fmaxf(v2, v3));
#pragma unroll
        for (int o = 16; o; o >>= 1) m = fmaxf(m, __shfl_xor_sync(0xffffffffu, m, o));
        float e0 = expf(v0 - m), e1 = expf(v1 - m);
        float e2 = expf(v2 - m), e3 = expf(v3 - m);
        float sum = e0 + e1 + e2 + e3;
#pragma unroll
        for (int o = 16; o; o >>= 1) sum += __shfl_xor_sync(0xffffffffu, sum, o);
        float rs = 1.0f / sum;
        size_t wb = (size_t)b * (NHEADS * NTOK * NTOK) + (size_t)h * (NTOK * NTOK) + (size_t)i * 128;
        W[wb + lane]      = e0 * rs;
        W[wb + lane + 32] = e1 * rs;
        W[wb + lane + 64] = e2 * rs;
        W[wb + lane + 96] = e3 * rs;
    }
}

// ---------------------------------------------------------------------------
// O[b,i,h*64+d] = sum_j attn[b,h,i,j] * v[b,j,h*64+d].  One block per (b,h).
// ---------------------------------------------------------------------------
__global__ __launch_bounds__(256) void av_kernel(const float* __restrict__ W,
                                                 const float* __restrict__ qkv,
                                                 float* __restrict__ O)
{
    int b = blockIdx.x >> 4, hh = blockIdx.x & 15;
    const float* attn = W + (size_t)blockIdx.x * (NTOK * NTOK);
    const float* vb = qkv + (size_t)b * NTOK * PATCHDIM + 2 * DIMV + hh * DHEAD;
    __shared__ float Ts[16][128];   // attn^T chunk: [j][i]
    __shared__ float Vs[16][64];    // v chunk:      [j][d]
    int tid = threadIdx.x, ty = tid >> 4, tx = tid & 15;
    int rr = tid >> 2, cc = tid & 3;

    float acc[8][4];
#pragma unroll
    for (int i = 0; i < 8; i++)
#pragma unroll
        for (int d = 0; d < 4; d++) acc[i][d] = 0.f;

    for (int jc = 0; jc < NTOK; jc += 16) {
#pragma unroll
        for (int it = 0; it < 2; it++) {
            int row = rr + it * 64;
            float4 a = *(const float4*)(attn + (size_t)row * 128 + jc + cc * 4);
            Ts[cc * 4 + 0][row] = a.x; Ts[cc * 4 + 1][row] = a.y;
            Ts[cc * 4 + 2][row] = a.z; Ts[cc * 4 + 3][row] = a.w;
        }
        {
            int jj = tid >> 4;     // 0..15
            int c4 = tid & 15;     // 0..15
            float4 v4 = *(const float4*)(vb + (size_t)(jc + jj) * PATCHDIM + c4 * 4);
            *(float4*)(&Vs[jj][c4 * 4]) = v4;
        }
        __syncthreads();
#pragma unroll
        for (int kk = 0; kk < 16; kk++) {
            float av8[8], vv[4];
            *(float4*)(av8)     = *(const float4*)&Ts[kk][ty * 8];
            *(float4*)(av8 + 4) = *(const float4*)&Ts[kk][ty * 8 + 4];
            *(float4*)(vv)      = *(const float4*)&Vs[kk][tx * 4];
#pragma unroll
            for (int i = 0; i < 8; i++)
#pragma unroll
                for (int d = 0; d < 4; d++) acc[i][d] += av8[i] * vv[d];
        }
        __syncthreads();
    }
#pragma unroll
    for (int i = 0; i < 8; i++) {
        int irow = ty * 8 + i;
        float4 outv = make_float4(acc[i][0], acc[i][1], acc[i][2], acc[i][3]);
        *(float4*)(O + (size_t)(b * 128 + irow) * DIMV + hh * DHEAD + tx * 4) = outv;
    }
}

// ---------------------------------------------------------------------------
// Reassemble: out[b,c,h*32+p1,w*32+p2] = Y[b*128 + h*16 + w][(p1*32+p2)*3 + c]
// ---------------------------------------------------------------------------
__global__ void reassemble_kernel(const float* __restrict__ Y, float* __restrict__ out)
{
    int idx = blockIdx.x * 256 + threadIdx.x;   // 32*3*256*512
    int xq = idx & 511;
    int rest = idx >> 9;
    int yr = rest & 255;
    rest >>= 8;
    int c = rest % 3;
    int b = rest / 3;
    int h = yr >> 5, p1 = yr & 31, w = xq >> 5, p2 = xq & 31;
    out[idx] = Y[(size_t)(b * 128 + h * 16 + w) * PATCHDIM + (p1 * 32 + p2) * 3 + c];
}

// ---------------------------------------------------------------------------
// Host launcher
// ---------------------------------------------------------------------------
extern "C" void kernel_launch(void* const* d_in, const int* in_sizes, int n_in,
                              void* d_out, int out_size)
{
    const float* img      = (const float*)d_in[0];
    const float* sph_pos  = (const float*)d_in[1];
    const float* sph_dist = (const float*)d_in[2];
    const float* conv_w   = (const float*)d_in[3];
    const float* conv_b   = (const float*)d_in[4];
    const float* nl_ln1_g = (const float*)d_in[5];
    const float* nl_ln1_b = (const float*)d_in[6];
    const float* nl_w     = (const float*)d_in[7];
    const float* nl_b     = (const float*)d_in[8];
    const float* nl_ln2_g = (const float*)d_in[9];
    const float* nl_ln2_b = (const float*)d_in[10];
    const float* pos_w    = (const float*)d_in[11];
    const float* pos_b    = (const float*)d_in[12];
    const float* ln_g     = (const float*)d_in[13];
    const float* ln_b     = (const float*)d_in[14];
    const float* wqkv     = (const float*)d_in[15];
    const float* wo       = (const float*)d_in[16];
    const float* wo_b     = (const float*)d_in[17];
    const float* tr_ln_g  = (const float*)d_in[18];
    const float* tr_ln_b  = (const float*)d_in[19];
    const float* exp_w    = (const float*)d_in[20];
    const float* exp_b    = (const float*)d_in[21];
    const float* out_ln_g = (const float*)d_in[22];
    const float* out_ln_b = (const float*)d_in[23];

    float *Xp, *qkv, *x, *h, *o, *w;
    cudaGetSymbolAddress((void**)&Xp,  g_big);
    cudaGetSymbolAddress((void**)&qkv, g_qkv);
    cudaGetSymbolAddress((void**)&x,   g_x);
    cudaGetSymbolAddress((void**)&h,   g_h);
    cudaGetSymbolAddress((void**)&o,   g_o);
    cudaGetSymbolAddress((void**)&w,   g_w);

    // 1. patch embedding
    extract_patches_kernel<<<ROWS * PATCHDIM / 256, 256>>>(img, Xp);
    gemm_kernel<true><<<dim3(DIMV / 128, ROWS / 128), 256>>>(
        Xp, conv_w, conv_b, nullptr, x, ROWS, DIMV, PATCHDIM);

    // 2. norm_linear + positional embedding
    ln_kernel<<<ROWS, 256>>>(x, nl_ln1_g, nl_ln1_b, h, DIMV);
    gemm_kernel<false><<<dim3(DIMV / 128, ROWS / 128), 256>>>(
        h, nl_w, nl_b, nullptr, x, ROWS, DIMV, DIMV);
    ln_kernel<<<ROWS, 256>>>(x, nl_ln2_g, nl_ln2_b, x, DIMV);
    add_pos_kernel<<<ROWS * DIMV / 256, 256>>>(x, sph_pos, pos_w, pos_b);

    // 3. transformer layers
    for (int l = 0; l < DEPTH; l++) {
        ln_kernel<<<ROWS, 256>>>(x, ln_g + l * DIMV, ln_b + l * DIMV, h, DIMV);
        gemm_kernel<false><<<dim3(PATCHDIM / 128, ROWS / 128), 256>>>(
            h, wqkv + (size_t)l * DIMV * PATCHDIM, nullptr, nullptr,
            qkv, ROWS, PATCHDIM, DIMV);
        qk_kernel<<<BATCH * NHEADS, 256>>>(qkv, sph_dist, w);
        std_softmax_kernel<<<BATCH * NTOK, 128>>>(w);
        av_kernel<<<BATCH * NHEADS, 256>>>(w, qkv, o);
        gemm_kernel<false><<<dim3(DIMV / 128, ROWS / 128), 256>>>(
            o, wo + (size_t)l * DIMV * DIMV, wo_b + l * DIMV, x,
            x, ROWS, DIMV, DIMV);
    }

    // 4. final LN + expand + output LN + reassembly
    ln_kernel<<<ROWS, 256>>>(x, tr_ln_g, tr_ln_b, h, DIMV);
    gemm_kernel<false><<<dim3(PATCHDIM / 128, ROWS / 128), 256>>>(
        h, exp_w, exp_b, nullptr, Xp, ROWS, PATCHDIM, DIMV);
    ln_kernel<<<ROWS, 256>>>(Xp, out_ln_g, out_ln_b, Xp, PATCHDIM);
    reassemble_kernel<<<32 * 3 * 256 * 512 / 256, 256>>>(Xp, (float*)d_out);
}

// round 4
// speedup vs baseline: 1.8725x; 1.8725x over previous
#include <cuda_runtime.h>
#include <cuda_bf16.h>
#include <cstdint>

// ---------------------------------------------------------------------------
// SphereViT forward — split-bf16 HMMA (mma.sync) GEMMs + fp32 SIMT attention.
// (tcgen05 unavailable: harness PTX target is compute_103 without 'a'.)
// ---------------------------------------------------------------------------

#define BATCH     32
#define NTOK      128
#define ROWS      4096
#define DIMV      1024
#define PATCHDIM  3072
#define NHEADS    16
#define DHEAD     64
#define DEPTH     12
#define LN_EPS    1e-5f

// -------------------- scratch (device globals; no allocs) ------------------
__device__ float g_big[ROWS * PATCHDIM];                 // expand output
__device__ float g_qkv[ROWS * PATCHDIM];                 // qkv per layer
__device__ float g_x  [ROWS * DIMV];                     // residual stream
__device__ float g_w  [BATCH * NHEADS * NTOK * NTOK];    // attention scores

// split-bf16 activations
__device__ __nv_bfloat16 g_Xph[ROWS * PATCHDIM], g_Xpl[ROWS * PATCHDIM];
__device__ __nv_bfloat16 g_hh [ROWS * DIMV],     g_hl [ROWS * DIMV];
__device__ __nv_bfloat16 g_oh [ROWS * DIMV],     g_ol [ROWS * DIMV];

// split-bf16 transposed weights ([N,K] K-major)
__device__ __nv_bfloat16 g_cwh[DIMV * PATCHDIM],          g_cwl[DIMV * PATCHDIM];
__device__ __nv_bfloat16 g_nlwh[DIMV * DIMV],             g_nlwl[DIMV * DIMV];
__device__ __nv_bfloat16 g_qwh[DEPTH * PATCHDIM * DIMV],  g_qwl[DEPTH * PATCHDIM * DIMV];
__device__ __nv_bfloat16 g_owh[DEPTH * DIMV * DIMV],      g_owl[DEPTH * DIMV * DIMV];
__device__ __nv_bfloat16 g_ewh[PATCHDIM * DIMV],          g_ewl[PATCHDIM * DIMV];

// ---------------------------------------------------------------------------
// PTX helpers (base sm_103 target: mma.sync / ldmatrix / cp.async only)
// ---------------------------------------------------------------------------
__device__ __forceinline__ uint32_t smem_u32(const void* p) {
    uint32_t a;
    asm("{ .reg .u64 t; cvta.to.shared.u64 t, %1; cvt.u32.u64 %0, t; }"
        : "=r"(a) : "l"(p));
    return a;
}

__device__ __forceinline__ void cpa16(uint32_t dst, const void* src) {
    asm volatile("cp.async.cg.shared.global [%0], [%1], 16;"
                 :: "r"(dst), "l"(src));
}
__device__ __forceinline__ void cp_commit() {
    asm volatile("cp.async.commit_group;");
}
template <int NN>
__device__ __forceinline__ void cp_wait() {
    asm volatile("cp.async.wait_group %0;" :: "n"(NN));
}

__device__ __forceinline__ void ldsm4(uint32_t* r, uint32_t addr) {
    asm volatile("ldmatrix.sync.aligned.m8n8.x4.shared.b16 {%0,%1,%2,%3}, [%4];"
                 : "=r"(r[0]), "=r"(r[1]), "=r"(r[2]), "=r"(r[3]) : "r"(addr));
}

__device__ __forceinline__ void mma16816(float* c, const uint32_t* a,
                                         const uint32_t* b) {
    asm volatile(
        "mma.sync.aligned.m16n8k16.row.col.f32.bf16.bf16.f32 "
        "{%0,%1,%2,%3}, {%4,%5,%6,%7}, {%8,%9}, {%0,%1,%2,%3};"
        : "+f"(c[0]), "+f"(c[1]), "+f"(c[2]), "+f"(c[3])
        : "r"(a[0]), "r"(a[1]), "r"(a[2]), "r"(a[3]), "r"(b[0]), "r"(b[1]));
}

// ---------------------------------------------------------------------------
// Split-bf16 HMMA GEMM: C[M,N] = (Ah+Al)[M,K] @ (Bh+Bl)[N,K]^T (+bias)(+res)
// BM=BN=128, BK=32, 256 threads (8 warps, 2x4), warp tile 64x32.
// 3-stage cp.async pipeline. SMEM per stage: 4 operands x 128x(32+8) bf16.
// ---------------------------------------------------------------------------
#define GPAD 8
#define GLDS (32 + GPAD)                 // 40 bf16 per row
#define OPND_ELEMS (128 * GLDS)          // 5120
#define STAGE_ELEMS (4 * OPND_ELEMS)     // 20480
#define HG_SMEM (3 * STAGE_ELEMS * 2)    // 122880 bytes

__global__ __launch_bounds__(256, 1) void hmma_gemm_kernel(
    const __nv_bfloat16* __restrict__ Ah, const __nv_bfloat16* __restrict__ Al,
    const __nv_bfloat16* __restrict__ Bh, const __nv_bfloat16* __restrict__ Bl,
    const float* __restrict__ bias, const float* __restrict__ res,
    float* __restrict__ C, int M, int N, int K)
{
    extern __shared__ __nv_bfloat16 smem[];
    const uint32_t sbase = smem_u32(smem);
    const int tid  = threadIdx.x;
    const int lane = tid & 31, warp = tid >> 5;
    const int wm = warp & 1, wn = warp >> 1;
    const int m0 = blockIdx.y << 7, n0 = blockIdx.x << 7;

    const __nv_bfloat16* g[4] = {
        Ah + (size_t)m0 * K, Al + (size_t)m0 * K,
        Bh + (size_t)n0 * K, Bl + (size_t)n0 * K };

    const int r0c = tid >> 2;            // 0..63
    const int c0c = tid & 3;             // 16B chunk

    auto issue = [&](int stage, int k0) {
#pragma unroll
        for (int op = 0; op < 4; op++) {
            uint32_t sdst = sbase + (uint32_t)(stage * STAGE_ELEMS + op * OPND_ELEMS) * 2;
            const __nv_bfloat16* gs = g[op];
#pragma unroll
            for (int half = 0; half < 2; half++) {
                int r = r0c + half * 64;
                cpa16(sdst + (uint32_t)(r * GLDS + c0c * 8) * 2,
                      gs + (size_t)r * K + k0 + c0c * 8);
            }
        }
    };

    float acc[4][4][4];
#pragma unroll
    for (int i = 0; i < 4; i++)
#pragma unroll
        for (int j = 0; j < 4; j++)
#pragma unroll
            for (int q = 0; q < 4; q++) acc[i][j][q] = 0.f;

    const int nk = K >> 5;
    issue(0, 0);  cp_commit();
    if (nk > 1) { issue(1, 32); cp_commit(); }
    else        { cp_commit(); }

    for (int it = 0; it < nk; ++it) {
        const int s = it % 3;
        if (it + 2 < nk) { issue((it + 2) % 3, (it + 2) << 5); cp_commit(); }
        else if (it + 2 == nk + 1) { /* nothing */ }
        else cp_commit();                  // keep group count uniform
        cp_wait<2>();
        __syncthreads();

        uint32_t sA  = sbase + (uint32_t)(s * STAGE_ELEMS) * 2;
        uint32_t sAl = sA + OPND_ELEMS * 2;
        uint32_t sB  = sA + 2 * OPND_ELEMS * 2;
        uint32_t sBl = sA + 3 * OPND_ELEMS * 2;

#pragma unroll
        for (int ks = 0; ks < 2; ks++) {
            uint32_t ah[4][4], al[4][4], bh[4][2], bl[4][2];
            const int arow = wm * 64 + (lane & 15);
            const int acol = ks * 16 + (lane >> 4) * 8;
#pragma unroll
            for (int mi = 0; mi < 4; mi++) {
                uint32_t off = (uint32_t)((arow + mi * 16) * GLDS + acol) * 2;
                ldsm4(ah[mi], sA  + off);
                ldsm4(al[mi], sAl + off);
            }
            const int brow = wn * 32 + ((lane >> 4) * 8) + (lane & 7);
            const int bcol = ks * 16 + ((lane >> 3) & 1) * 8;
#pragma unroll
            for (int gp = 0; gp < 2; gp++) {
                uint32_t off = (uint32_t)((brow + gp * 16) * GLDS + bcol) * 2;
                uint32_t rh[4], rl[4];
                ldsm4(rh, sB  + off);
                ldsm4(rl, sBl + off);
                bh[gp*2][0] = rh[0]; bh[gp*2][1] = rh[1];
                bh[gp*2+1][0] = rh[2]; bh[gp*2+1][1] = rh[3];
                bl[gp*2][0] = rl[0]; bl[gp*2][1] = rl[1];
                bl[gp*2+1][0] = rl[2]; bl[gp*2+1][1] = rl[3];
            }
#pragma unroll
            for (int mi = 0; mi < 4; mi++)
#pragma unroll
                for (int nj = 0; nj < 4; nj++) {
                    mma16816(acc[mi][nj], ah[mi], bh[nj]);
                    mma16816(acc[mi][nj], ah[mi], bl[nj]);
                    mma16816(acc[mi][nj], al[mi], bh[nj]);
                }
        }
        __syncthreads();
    }

    // epilogue
#pragma unroll
    for (int mi = 0; mi < 4; mi++) {
        int r0 = m0 + wm * 64 + mi * 16 + (lane >> 2);
#pragma unroll
        for (int nj = 0; nj < 4; nj++) {
            int c = n0 + wn * 32 + nj * 8 + (lane & 3) * 2;
            float v0x = acc[mi][nj][0], v0y = acc[mi][nj][1];
            float v1x = acc[mi][nj][2], v1y = acc[mi][nj][3];
            if (bias) {
                float bx = bias[c], by = bias[c + 1];
                v0x += bx; v0y += by; v1x += bx; v1y += by;
            }
            size_t o0 = (size_t)r0 * N + c;
            size_t o1 = o0 + (size_t)8 * N;
            if (res) {
                float2 ra = *(const float2*)(res + o0);
                float2 rb = *(const float2*)(res + o1);
                v0x += ra.x; v0y += ra.y; v1x += rb.x; v1y += rb.y;
            }
            *(float2*)(C + o0) = make_float2(v0x, v0y);
            *(float2*)(C + o1) = make_float2(v1x, v1y);
        }
    }
}

// ---------------------------------------------------------------------------
// Weight prep: split and transpose+split into bf16 hi/lo
// ---------------------------------------------------------------------------
__global__ void split_kernel(const float* __restrict__ X,
                             __nv_bfloat16* __restrict__ H,
                             __nv_bfloat16* __restrict__ L) {
    size_t i = (size_t)blockIdx.x * 256 + threadIdx.x;
    float v = X[i];
    __nv_bfloat16 h = __float2bfloat16(v);
    H[i] = h;
    L[i] = __float2bfloat16(v - __bfloat162float(h));
}

// W [L][K][N] fp32 -> T [L][N][K] bf16 hi/lo.  grid (N/32, K/32, L), block (32,8)
__global__ void wtrans_split_kernel(const float* __restrict__ W,
                                    __nv_bfloat16* __restrict__ Th,
                                    __nv_bfloat16* __restrict__ Tl,
                                    int K, int N) {
    __shared__ float t[32][33];
    const float* Wl = W + (size_t)blockIdx.z * K * N;
    size_t ob = (size_t)blockIdx.z * K * N;
    int x = blockIdx.x * 32 + threadIdx.x;   // N
    int y = blockIdx.y * 32 + threadIdx.y;   // K
#pragma unroll
    for (int j = 0; j < 32; j += 8)
        t[threadIdx.y + j][threadIdx.x] = Wl[(size_t)(y + j) * N + x];
    __syncthreads();
    int n = blockIdx.x * 32 + threadIdx.y;
    int k = blockIdx.y * 32 + threadIdx.x;
#pragma unroll
    for (int j = 0; j < 32; j += 8) {
        float v = t[threadIdx.x][threadIdx.y + j];
        __nv_bfloat16 h = __float2bfloat16(v);
        size_t o = ob + (size_t)(n + j) * K + k;
        Th[o] = h;
        Tl[o] = __float2bfloat16(v - __bfloat162float(h));
    }
}

// ---------------------------------------------------------------------------
// Patch extraction with split
// ---------------------------------------------------------------------------
__global__ void extract_patches_kernel(const float* __restrict__ img,
                                       __nv_bfloat16* __restrict__ H,
                                       __nv_bfloat16* __restrict__ L) {
    int idx = blockIdx.x * 256 + threadIdx.x;
    int col = idx % PATCHDIM;
    int row = idx / PATCHDIM;
    int b = row >> 7, t = row & 127;
    int h = t >> 4, w = t & 15;
    int c = col >> 10, r = col & 1023;
    int p = r >> 5, q = r & 31;
    float v = img[(((size_t)b * 3 + c) * 256 + h * 32 + p) * 512 + w * 32 + q];
    __nv_bfloat16 hh = __float2bfloat16(v);
    H[idx] = hh;
    L[idx] = __float2bfloat16(v - __bfloat162float(hh));
}

// ---------------------------------------------------------------------------
// LayerNorm
// ---------------------------------------------------------------------------
__device__ __forceinline__ void ln_stats(const float* __restrict__ x, size_t base,
                                         int D, float& mu, float& rstd) {
    float s = 0.f, ss = 0.f;
    for (int i = threadIdx.x; i < D; i += 256) {
        float v = x[base + i];
        s += v; ss += v * v;
    }
#pragma unroll
    for (int o = 16; o; o >>= 1) {
        s  += __shfl_xor_sync(0xffffffffu, s, o);
        ss += __shfl_xor_sync(0xffffffffu, ss, o);
    }
    __shared__ float sh[2][8];
    int w = threadIdx.x >> 5;
    if ((threadIdx.x & 31) == 0) { sh[0][w] = s; sh[1][w] = ss; }
    __syncthreads();
    if (threadIdx.x < 32) {
        s  = (threadIdx.x < 8) ? sh[0][threadIdx.x] : 0.f;
        ss = (threadIdx.x < 8) ? sh[1][threadIdx.x] : 0.f;
#pragma unroll
        for (int o = 4; o; o >>= 1) {
            s  += __shfl_xor_sync(0xffffffffu, s, o);
            ss += __shfl_xor_sync(0xffffffffu, ss, o);
        }
        if (threadIdx.x == 0) { sh[0][0] = s; sh[1][0] = ss; }
    }
    __syncthreads();
    s = sh[0][0]; ss = sh[1][0];
    float invD = 1.0f / (float)D;
    mu = s * invD;
    float var = ss * invD - mu * mu;
    rstd = rsqrtf(var + LN_EPS);
}

__global__ void ln_kernel(const float* __restrict__ x, const float* __restrict__ g,
                          const float* __restrict__ beta, float* __restrict__ y, int D) {
    size_t base = (size_t)blockIdx.x * D;
    float mu, rstd;
    ln_stats(x, base, D, mu, rstd);
    for (int i = threadIdx.x; i < D; i += 256)
        y[base + i] = (x[base + i] - mu) * rstd * g[i] + beta[i];
}

__global__ void ln_split_kernel(const float* __restrict__ x, const float* __restrict__ g,
                                const float* __restrict__ beta,
                                __nv_bfloat16* __restrict__ H,
                                __nv_bfloat16* __restrict__ L, int D) {
    size_t base = (size_t)blockIdx.x * D;
    float mu, rstd;
    ln_stats(x, base, D, mu, rstd);
    for (int i = threadIdx.x; i < D; i += 256) {
        float v = (x[base + i] - mu) * rstd * g[i] + beta[i];
        __nv_bfloat16 h = __float2bfloat16(v);
        H[base + i] = h;
        L[base + i] = __float2bfloat16(v - __bfloat162float(h));
    }
}

// ---------------------------------------------------------------------------
// x[row][d] += sph_pos[row%128] @ pos_w + pos_b
// ---------------------------------------------------------------------------
__global__ void add_pos_kernel(float* __restrict__ x, const float* __restrict__ sph_pos,
                               const float* __restrict__ pos_w,
                               const float* __restrict__ pos_b) {
    int idx = blockIdx.x * 256 + threadIdx.x;
    int d = idx & 1023;
    int i = (idx >> 10) & 127;
    x[idx] += sph_pos[i * 2] * pos_w[d] + sph_pos[i * 2 + 1] * pos_w[1024 + d] + pos_b[d];
}

// ---------------------------------------------------------------------------
// W[b,h,i,j] = (q_i . k_j) * 0.125 * (1 + dist[i,j]).  One block per (b,h).
// ---------------------------------------------------------------------------
__global__ __launch_bounds__(256) void qk_kernel(const float* __restrict__ qkv,
                                                 const float* __restrict__ dist,
                                                 float* __restrict__ W) {
    int b = blockIdx.x >> 4, hh = blockIdx.x & 15;
    const float* qb = qkv + (size_t)b * NTOK * PATCHDIM + hh * DHEAD;
    const float* kb = qb + DIMV;
    __shared__ float Qs[16][128];
    __shared__ float Ks[16][128];
    int tid = threadIdx.x, ty = tid >> 4, tx = tid & 15;
    int rr = tid >> 2, cc = tid & 3;

    float acc[8][8];
#pragma unroll
    for (int i = 0; i < 8; i++)
#pragma unroll
        for (int j = 0; j < 8; j++) acc[i][j] = 0.f;

    for (int kc = 0; kc < DHEAD; kc += 16) {
#pragma unroll
        for (int it = 0; it < 2; it++) {
            int row = rr + it * 64;
            float4 a = *(const float4*)(qb + (size_t)row * PATCHDIM + kc + cc * 4);
            Qs[cc*4+0][row] = a.x; Qs[cc*4+1][row] = a.y;
            Qs[cc*4+2][row] = a.z; Qs[cc*4+3][row] = a.w;
            float4 k4 = *(const float4*)(kb + (size_t)row * PATCHDIM + kc + cc * 4);
            Ks[cc*4+0][row] = k4.x; Ks[cc*4+1][row] = k4.y;
            Ks[cc*4+2][row] = k4.z; Ks[cc*4+3][row] = k4.w;
        }
        __syncthreads();
#pragma unroll
        for (int kk = 0; kk < 16; kk++) {
            float av[8], bv[8];
            *(float4*)(av)     = *(const float4*)&Qs[kk][ty * 8];
            *(float4*)(av + 4) = *(const float4*)&Qs[kk][ty * 8 + 4];
            *(float4*)(bv)     = *(const float4*)&Ks[kk][tx * 8];
            *(float4*)(bv + 4) = *(const float4*)&Ks[kk][tx * 8 + 4];
#pragma unroll
            for (int i = 0; i < 8; i++)
#pragma unroll
                for (int j = 0; j < 8; j++) acc[i][j] += av[i] * bv[j];
        }
        __syncthreads();
    }

    size_t wbase = (size_t)blockIdx.x * (NTOK * NTOK);
#pragma unroll
    for (int i = 0; i < 8; i++) {
        int irow = ty * 8 + i;
#pragma unroll
        for (int j = 0; j < 8; j++) {
            int jcol = tx * 8 + j;
            W[wbase + irow * 128 + jcol] =
                acc[i][j] * 0.125f * (1.0f + dist[irow * 128 + jcol]);
        }
    }
}

// ---------------------------------------------------------------------------
// Cross-head standardize (ddof=1) + softmax over j. Block per (b,i). In-place.
// ---------------------------------------------------------------------------
__global__ __launch_bounds__(128) void std_softmax_kernel(float* __restrict__ W) {
    int b = blockIdx.x >> 7, i = blockIdx.x & 127;
    int j = threadIdx.x;
    __shared__ float sm[NHEADS][128];

    size_t base = (size_t)b * (NHEADS * NTOK * NTOK) + (size_t)i * 128 + j;
    float vals[NHEADS];
    float s = 0.f;
#pragma unroll
    for (int h = 0; h < NHEADS; h++) {
        float v = W[base + (size_t)h * (NTOK * NTOK)];
        vals[h] = v; s += v;
    }
    float mu = s * (1.0f / 16.0f);
    float d2 = 0.f;
#pragma unroll
    for (int h = 0; h < NHEADS; h++) {
        float d = vals[h] - mu;
        d2 += d * d;
    }
    float inv = rsqrtf(d2 * (1.0f / 15.0f));
#pragma unroll
    for (int h = 0; h < NHEADS; h++) sm[h][j] = (vals[h] - mu) * inv;
    __syncthreads();

    int warp = j >> 5, lane = j & 31;
#pragma unroll
    for (int r = 0; r < 4; r++) {
        int h = warp * 4 + r;
        float v0 = sm[h][lane], v1 = sm[h][lane + 32];
        float v2 = sm[h][lane + 64], v3 = sm[h][lane + 96];
        float m = fmaxf(fmaxf(v0, v1), fmaxf(v2, v3));
#pragma unroll
        for (int o = 16; o; o >>= 1) m = fmaxf(m, __shfl_xor_sync(0xffffffffu, m, o));
        float e0 = expf(v0 - m), e1 = expf(v1 - m);
        float e2 = expf(v2 - m), e3 = expf(v3 - m);
        float sum = e0 + e1 + e2 + e3;
#pragma unroll
        for (int o = 16; o; o >>= 1) sum += __shfl_xor_sync(0xffffffffu, sum, o);
        float rs = 1.0f / sum;
        size_t wb = (size_t)b * (NHEADS * NTOK * NTOK) + (size_t)h * (NTOK * NTOK)
                  + (size_t)i * 128;
        W[wb + lane]      = e0 * rs;
        W[wb + lane + 32] = e1 * rs;
        W[wb + lane + 64] = e2 * rs;
        W[wb + lane + 96] = e3 * rs;
    }
}

// ---------------------------------------------------------------------------
// O (split bf16) = attn @ v.  One block per (b,h).
// ---------------------------------------------------------------------------
__global__ __launch_bounds__(256) void av_kernel(const float* __restrict__ W,
                                                 const float* __restrict__ qkv,
                                                 __nv_bfloat16* __restrict__ Oh,
                                                 __nv_bfloat16* __restrict__ Ol) {
    int b = blockIdx.x >> 4, hh = blockIdx.x & 15;
    const float* attn = W + (size_t)blockIdx.x * (NTOK * NTOK);
    const float* vb = qkv + (size_t)b * NTOK * PATCHDIM + 2 * DIMV + hh * DHEAD;
    __shared__ float Ts[16][128];
    __shared__ float Vs[16][64];
    int tid = threadIdx.x, ty = tid >> 4, tx = tid & 15;
    int rr = tid >> 2, cc = tid & 3;

    float acc[8][4];
#pragma unroll
    for (int i = 0; i < 8; i++)
#pragma unroll
        for (int d = 0; d < 4; d++) acc[i][d] = 0.f;

    for (int jc = 0; jc < NTOK; jc += 16) {
#pragma unroll
        for (int it = 0; it < 2; it++) {
            int row = rr + it * 64;
            float4 a = *(const float4*)(attn + (size_t)row * 128 + jc + cc * 4);
            Ts[cc*4+0][row] = a.x; Ts[cc*4+1][row] = a.y;
            Ts[cc*4+2][row] = a.z; Ts[cc*4+3][row] = a.w;
        }
        {
            int jj = tid >> 4;
            int c4 = tid & 15;
            float4 v4 = *(const float4*)(vb + (size_t)(jc + jj) * PATCHDIM + c4 * 4);
            *(float4*)(&Vs[jj][c4 * 4]) = v4;
        }
        __syncthreads();
#pragma unroll
        for (int kk = 0; kk < 16; kk++) {
            float av8[8], vv[4];
            *(float4*)(av8)     = *(const float4*)&Ts[kk][ty * 8];
            *(float4*)(av8 + 4) = *(const float4*)&Ts[kk][ty * 8 + 4];
            *(float4*)(vv)      = *(const float4*)&Vs[kk][tx * 4];
#pragma unroll
            for (int i = 0; i < 8; i++)
#pragma unroll
                for (int d = 0; d < 4; d++) acc[i][d] += av8[i] * vv[d];
        }
        __syncthreads();
    }
#pragma unroll
    for (int i = 0; i < 8; i++) {
        int irow = ty * 8 + i;
        size_t ob = (size_t)(b * 128 + irow) * DIMV + hh * DHEAD + tx * 4;
#pragma unroll
        for (int d = 0; d < 4; d++) {
            float v = acc[i][d];
            __nv_bfloat16 h = __float2bfloat16(v);
            Oh[ob + d] = h;
            Ol[ob + d] = __float2bfloat16(v - __bfloat162float(h));
        }
    }
}

// ---------------------------------------------------------------------------
// Reassemble: out[b,c,h*32+p1,w*32+p2] = Y[b*128+h*16+w][(p1*32+p2)*3 + c]
// ---------------------------------------------------------------------------
__global__ void reassemble_kernel(const float* __restrict__ Y, float* __restrict__ out) {
    int idx = blockIdx.x * 256 + threadIdx.x;
    int xq = idx & 511;
    int rest = idx >> 9;
    int yr = rest & 255;
    rest >>= 8;
    int c = rest % 3;
    int b = rest / 3;
    int h = yr >> 5, p1 = yr & 31, w = xq >> 5, p2 = xq & 31;
    out[idx] = Y[(size_t)(b * 128 + h * 16 + w) * PATCHDIM + (p1 * 32 + p2) * 3 + c];
}

// ---------------------------------------------------------------------------
// Host launcher
// ---------------------------------------------------------------------------
extern "C" void kernel_launch(void* const* d_in, const int* in_sizes, int n_in,
                              void* d_out, int out_size)
{
    const float* img      = (const float*)d_in[0];
    const float* sph_pos  = (const float*)d_in[1];
    const float* sph_dist = (const float*)d_in[2];
    const float* conv_w   = (const float*)d_in[3];
    const float* conv_b   = (const float*)d_in[4];
    const float* nl_ln1_g = (const float*)d_in[5];
    const float* nl_ln1_b = (const float*)d_in[6];
    const float* nl_w     = (const float*)d_in[7];
    const float* nl_b     = (const float*)d_in[8];
    const float* nl_ln2_g = (const float*)d_in[9];
    const float* nl_ln2_b = (const float*)d_in[10];
    const float* pos_w    = (const float*)d_in[11];
    const float* pos_b    = (const float*)d_in[12];
    const float* ln_g     = (const float*)d_in[13];
    const float* ln_b     = (const float*)d_in[14];
    const float* wqkv     = (const float*)d_in[15];
    const float* wo       = (const float*)d_in[16];
    const float* wo_b     = (const float*)d_in[17];
    const float* tr_ln_g  = (const float*)d_in[18];
    const float* tr_ln_b  = (const float*)d_in[19];
    const float* exp_w    = (const float*)d_in[20];
    const float* exp_b    = (const float*)d_in[21];
    const float* out_ln_g = (const float*)d_in[22];
    const float* out_ln_b = (const float*)d_in[23];

    float *big, *qkv, *x, *w;
    cudaGetSymbolAddress((void**)&big, g_big);
    cudaGetSymbolAddress((void**)&qkv, g_qkv);
    cudaGetSymbolAddress((void**)&x,   g_x);
    cudaGetSymbolAddress((void**)&w,   g_w);
    __nv_bfloat16 *Xph, *Xpl, *hh, *hl, *oh, *ol;
    __nv_bfloat16 *cwh, *cwl, *nlwh, *nlwl, *qwh, *qwl, *owh, *owl, *ewh, *ewl;
    cudaGetSymbolAddress((void**)&Xph, g_Xph);  cudaGetSymbolAddress((void**)&Xpl, g_Xpl);
    cudaGetSymbolAddress((void**)&hh,  g_hh);   cudaGetSymbolAddress((void**)&hl,  g_hl);
    cudaGetSymbolAddress((void**)&oh,  g_oh);   cudaGetSymbolAddress((void**)&ol,  g_ol);
    cudaGetSymbolAddress((void**)&cwh, g_cwh);  cudaGetSymbolAddress((void**)&cwl, g_cwl);
    cudaGetSymbolAddress((void**)&nlwh,g_nlwh); cudaGetSymbolAddress((void**)&nlwl,g_nlwl);
    cudaGetSymbolAddress((void**)&qwh, g_qwh);  cudaGetSymbolAddress((void**)&qwl, g_qwl);
    cudaGetSymbolAddress((void**)&owh, g_owh);  cudaGetSymbolAddress((void**)&owl, g_owl);
    cudaGetSymbolAddress((void**)&ewh, g_ewh);  cudaGetSymbolAddress((void**)&ewl, g_ewl);

    cudaFuncSetAttribute(hmma_gemm_kernel,
                         cudaFuncAttributeMaxDynamicSharedMemorySize, HG_SMEM);

    // ---- weight prep (bf16 hi/lo, transposed to [N,K]) ----
    split_kernel<<<DIMV * PATCHDIM / 256, 256>>>(conv_w, cwh, cwl);   // already [N,K]
    wtrans_split_kernel<<<dim3(DIMV/32, DIMV/32, 1),     dim3(32,8)>>>(nl_w,  nlwh, nlwl, DIMV, DIMV);
    wtrans_split_kernel<<<dim3(PATCHDIM/32, DIMV/32, DEPTH), dim3(32,8)>>>(wqkv, qwh, qwl, DIMV, PATCHDIM);
    wtrans_split_kernel<<<dim3(DIMV/32, DIMV/32, DEPTH), dim3(32,8)>>>(wo,    owh,  owl,  DIMV, DIMV);
    wtrans_split_kernel<<<dim3(PATCHDIM/32, DIMV/32, 1), dim3(32,8)>>>(exp_w, ewh,  ewl,  DIMV, PATCHDIM);

    // ---- patch embedding ----
    extract_patches_kernel<<<ROWS * PATCHDIM / 256, 256>>>(img, Xph, Xpl);
    hmma_gemm_kernel<<<dim3(DIMV/128, ROWS/128), 256, HG_SMEM>>>(
        Xph, Xpl, cwh, cwl, conv_b, nullptr, x, ROWS, DIMV, PATCHDIM);

    // ---- norm_linear + positional embedding ----
    ln_split_kernel<<<ROWS, 256>>>(x, nl_ln1_g, nl_ln1_b, hh, hl, DIMV);
    hmma_gemm_kernel<<<dim3(DIMV/128, ROWS/128), 256, HG_SMEM>>>(
        hh, hl, nlwh, nlwl, nl_b, nullptr, x, ROWS, DIMV, DIMV);
    ln_kernel<<<ROWS, 256>>>(x, nl_ln2_g, nl_ln2_b, x, DIMV);
    add_pos_kernel<<<ROWS * DIMV / 256, 256>>>(x, sph_pos, pos_w, pos_b);

    // ---- transformer layers ----
    for (int l = 0; l < DEPTH; l++) {
        ln_split_kernel<<<ROWS, 256>>>(x, ln_g + l * DIMV, ln_b + l * DIMV, hh, hl, DIMV);
        hmma_gemm_kernel<<<dim3(PATCHDIM/128, ROWS/128), 256, HG_SMEM>>>(
            hh, hl, qwh + (size_t)l * PATCHDIM * DIMV, qwl + (size_t)l * PATCHDIM * DIMV,
            nullptr, nullptr, qkv, ROWS, PATCHDIM, DIMV);
        qk_kernel<<<BATCH * NHEADS, 256>>>(qkv, sph_dist, w);
        std_softmax_kernel<<<BATCH * NTOK, 128>>>(w);
        av_kernel<<<BATCH * NHEADS, 256>>>(w, qkv, oh, ol);
        hmma_gemm_kernel<<<dim3(DIMV/128, ROWS/128), 256, HG_SMEM>>>(
            oh, ol, owh + (size_t)l * DIMV * DIMV, owl + (size_t)l * DIMV * DIMV,
            wo_b + l * DIMV, x, x, ROWS, DIMV, DIMV);
    }

    // ---- final LN + expand + output LN + reassembly ----
    ln_split_kernel<<<ROWS, 256>>>(x, tr_ln_g, tr_ln_b, hh, hl, DIMV);
    hmma_gemm_kernel<<<dim3(PATCHDIM/128, ROWS/128), 256, HG_SMEM>>>(
        hh, hl, ewh, ewl, exp_b, nullptr, big, ROWS, PATCHDIM, DIMV);
    ln_kernel<<<ROWS, 256>>>(big, out_ln_g, out_ln_b, big, PATCHDIM);
    reassemble_kernel<<<ROWS * PATCHDIM / 256, 256>>>(big, (float*)d_out);
}

// round 5
// speedup vs baseline: 2.0724x; 1.1068x over previous
#include <cuda_runtime.h>
#include <cuda_bf16.h>
#include <cstdint>

// ---------------------------------------------------------------------------
// SphereViT forward — split-bf16 HMMA (mma.sync) GEMMs + fp32 SIMT attention.
// R5: 3-pass MMA ordering (break same-acc RAW chains), 2-stage pipeline,
//     2 CTAs/SM via __launch_bounds__(256,2).
// ---------------------------------------------------------------------------

#define BATCH     32
#define NTOK      128
#define ROWS      4096
#define DIMV      1024
#define PATCHDIM  3072
#define NHEADS    16
#define DHEAD     64
#define DEPTH     12
#define LN_EPS    1e-5f

// -------------------- scratch (device globals; no allocs) ------------------
__device__ float g_big[ROWS * PATCHDIM];                 // expand output
__device__ float g_qkv[ROWS * PATCHDIM];                 // qkv per layer
__device__ float g_x  [ROWS * DIMV];                     // residual stream
__device__ float g_w  [BATCH * NHEADS * NTOK * NTOK];    // attention scores

// split-bf16 activations
__device__ __nv_bfloat16 g_Xph[ROWS * PATCHDIM], g_Xpl[ROWS * PATCHDIM];
__device__ __nv_bfloat16 g_hh [ROWS * DIMV],     g_hl [ROWS * DIMV];
__device__ __nv_bfloat16 g_oh [ROWS * DIMV],     g_ol [ROWS * DIMV];

// split-bf16 transposed weights ([N,K] K-major)
__device__ __nv_bfloat16 g_cwh[DIMV * PATCHDIM],          g_cwl[DIMV * PATCHDIM];
__device__ __nv_bfloat16 g_nlwh[DIMV * DIMV],             g_nlwl[DIMV * DIMV];
__device__ __nv_bfloat16 g_qwh[DEPTH * PATCHDIM * DIMV],  g_qwl[DEPTH * PATCHDIM * DIMV];
__device__ __nv_bfloat16 g_owh[DEPTH * DIMV * DIMV],      g_owl[DEPTH * DIMV * DIMV];
__device__ __nv_bfloat16 g_ewh[PATCHDIM * DIMV],          g_ewl[PATCHDIM * DIMV];

// ---------------------------------------------------------------------------
// PTX helpers
// ---------------------------------------------------------------------------
__device__ __forceinline__ uint32_t smem_u32(const void* p) {
    uint32_t a;
    asm("{ .reg .u64 t; cvta.to.shared.u64 t, %1; cvt.u32.u64 %0, t; }"
        : "=r"(a) : "l"(p));
    return a;
}

__device__ __forceinline__ void cpa16(uint32_t dst, const void* src) {
    asm volatile("cp.async.cg.shared.global [%0], [%1], 16;"
                 :: "r"(dst), "l"(src));
}
__device__ __forceinline__ void cp_commit() {
    asm volatile("cp.async.commit_group;");
}
template <int NN>
__device__ __forceinline__ void cp_wait() {
    asm volatile("cp.async.wait_group %0;" :: "n"(NN));
}

__device__ __forceinline__ void ldsm4(uint32_t* r, uint32_t addr) {
    asm volatile("ldmatrix.sync.aligned.m8n8.x4.shared.b16 {%0,%1,%2,%3}, [%4];"
                 : "=r"(r[0]), "=r"(r[1]), "=r"(r[2]), "=r"(r[3]) : "r"(addr));
}

__device__ __forceinline__ void mma16816(float* c, const uint32_t* a,
                                         const uint32_t* b) {
    asm volatile(
        "mma.sync.aligned.m16n8k16.row.col.f32.bf16.bf16.f32 "
        "{%0,%1,%2,%3}, {%4,%5,%6,%7}, {%8,%9}, {%0,%1,%2,%3};"
        : "+f"(c[0]), "+f"(c[1]), "+f"(c[2]), "+f"(c[3])
        : "r"(a[0]), "r"(a[1]), "r"(a[2]), "r"(a[3]), "r"(b[0]), "r"(b[1]));
}

// ---------------------------------------------------------------------------
// Split-bf16 HMMA GEMM: C[M,N] = (Ah+Al)[M,K] @ (Bh+Bl)[N,K]^T (+bias)(+res)
// BM=BN=128, BK=32, 256 threads (8 warps, 2x4), warp tile 64x32.
// 2-stage cp.async pipeline, 2 CTAs/SM.
// ---------------------------------------------------------------------------
#define GPAD 8
#define GLDS (32 + GPAD)                 // 40 bf16 per row
#define OPND_ELEMS (128 * GLDS)          // 5120
#define STAGE_ELEMS (4 * OPND_ELEMS)     // 20480
#define HG_SMEM (2 * STAGE_ELEMS * 2)    // 81920 bytes

__global__ __launch_bounds__(256, 2) void hmma_gemm_kernel(
    const __nv_bfloat16* __restrict__ Ah, const __nv_bfloat16* __restrict__ Al,
    const __nv_bfloat16* __restrict__ Bh, const __nv_bfloat16* __restrict__ Bl,
    const float* __restrict__ bias, const float* __restrict__ res,
    float* __restrict__ C, int M, int N, int K)
{
    extern __shared__ __nv_bfloat16 smem[];
    const uint32_t sbase = smem_u32(smem);
    const int tid  = threadIdx.x;
    const int lane = tid & 31, warp = tid >> 5;
    const int wm = warp & 1, wn = warp >> 1;
    const int m0 = blockIdx.y << 7, n0 = blockIdx.x << 7;

    const __nv_bfloat16* g[4] = {
        Ah + (size_t)m0 * K, Al + (size_t)m0 * K,
        Bh + (size_t)n0 * K, Bl + (size_t)n0 * K };

    const int r0c = tid >> 2;            // 0..63
    const int c0c = tid & 3;             // 16B chunk

    auto issue = [&](int stage, int k0) {
#pragma unroll
        for (int op = 0; op < 4; op++) {
            uint32_t sdst = sbase + (uint32_t)(stage * STAGE_ELEMS + op * OPND_ELEMS) * 2;
            const __nv_bfloat16* gs = g[op];
#pragma unroll
            for (int half = 0; half < 2; half++) {
                int r = r0c + half * 64;
                cpa16(sdst + (uint32_t)(r * GLDS + c0c * 8) * 2,
                      gs + (size_t)r * K + k0 + c0c * 8);
            }
        }
    };

    float acc[4][4][4];
#pragma unroll
    for (int i = 0; i < 4; i++)
#pragma unroll
        for (int j = 0; j < 4; j++)
#pragma unroll
            for (int q = 0; q < 4; q++) acc[i][j][q] = 0.f;

    const int nk = K >> 5;
    issue(0, 0);
    cp_commit();

    // fragment addressing (constant across iters except stage base)
    const int arow = wm * 64 + (lane & 15);
    const int acolb = (lane >> 4) * 8;
    const int brow = wn * 32 + ((lane >> 4) * 8) + (lane & 7);
    const int bcolb = ((lane >> 3) & 1) * 8;

    for (int it = 0; it < nk; ++it) {
        const int s = it & 1;
        if (it + 1 < nk) {
            issue(s ^ 1, (it + 1) << 5);
            cp_commit();
            cp_wait<1>();
        } else {
            cp_wait<0>();
        }
        __syncthreads();

        uint32_t sA  = sbase + (uint32_t)(s * STAGE_ELEMS) * 2;
        uint32_t sAl = sA + OPND_ELEMS * 2;
        uint32_t sB  = sA + 2 * OPND_ELEMS * 2;
        uint32_t sBl = sA + 3 * OPND_ELEMS * 2;

#pragma unroll
        for (int ks = 0; ks < 2; ks++) {
            const int acol = ks * 16 + acolb;
            const int bcol = ks * 16 + bcolb;
            uint32_t ah[4][4], bh[4][2];
#pragma unroll
            for (int mi = 0; mi < 4; mi++)
                ldsm4(ah[mi], sA + (uint32_t)((arow + mi * 16) * GLDS + acol) * 2);
#pragma unroll
            for (int gp = 0; gp < 2; gp++) {
                uint32_t rh[4];
                ldsm4(rh, sB + (uint32_t)((brow + gp * 16) * GLDS + bcol) * 2);
                bh[gp*2][0] = rh[0]; bh[gp*2][1] = rh[1];
                bh[gp*2+1][0] = rh[2]; bh[gp*2+1][1] = rh[3];
            }
            // pass 1: hi*hi — 16 independent accs
#pragma unroll
            for (int mi = 0; mi < 4; mi++)
#pragma unroll
                for (int nj = 0; nj < 4; nj++)
                    mma16816(acc[mi][nj], ah[mi], bh[nj]);

            // pass 2: hi*lo
            uint32_t bl[4][2];
#pragma unroll
            for (int gp = 0; gp < 2; gp++) {
                uint32_t rl[4];
                ldsm4(rl, sBl + (uint32_t)((brow + gp * 16) * GLDS + bcol) * 2);
                bl[gp*2][0] = rl[0]; bl[gp*2][1] = rl[1];
                bl[gp*2+1][0] = rl[2]; bl[gp*2+1][1] = rl[3];
            }
#pragma unroll
            for (int mi = 0; mi < 4; mi++)
#pragma unroll
                for (int nj = 0; nj < 4; nj++)
                    mma16816(acc[mi][nj], ah[mi], bl[nj]);

            // pass 3: lo*hi (ah dead now; al reuses its registers)
            uint32_t al[4][4];
#pragma unroll
            for (int mi = 0; mi < 4; mi++)
                ldsm4(al[mi], sAl + (uint32_t)((arow + mi * 16) * GLDS + acol) * 2);
#pragma unroll
            for (int mi = 0; mi < 4; mi++)
#pragma unroll
                for (int nj = 0; nj < 4; nj++)
                    mma16816(acc[mi][nj], al[mi], bh[nj]);
        }
        __syncthreads();
    }

    // epilogue
#pragma unroll
    for (int mi = 0; mi < 4; mi++) {
        int r0 = m0 + wm * 64 + mi * 16 + (lane >> 2);
#pragma unroll
        for (int nj = 0; nj < 4; nj++) {
            int c = n0 + wn * 32 + nj * 8 + (lane & 3) * 2;
            float v0x = acc[mi][nj][0], v0y = acc[mi][nj][1];
            float v1x = acc[mi][nj][2], v1y = acc[mi][nj][3];
            if (bias) {
                float bx = bias[c], by = bias[c + 1];
                v0x += bx; v0y += by; v1x += bx; v1y += by;
            }
            size_t o0 = (size_t)r0 * N + c;
            size_t o1 = o0 + (size_t)8 * N;
            if (res) {
                float2 ra = *(const float2*)(res + o0);
                float2 rb = *(const float2*)(res + o1);
                v0x += ra.x; v0y += ra.y; v1x += rb.x; v1y += rb.y;
            }
            *(float2*)(C + o0) = make_float2(v0x, v0y);
            *(float2*)(C + o1) = make_float2(v1x, v1y);
        }
    }
}

// ---------------------------------------------------------------------------
// Weight prep: split and transpose+split into bf16 hi/lo
// ---------------------------------------------------------------------------
__global__ void split_kernel(const float* __restrict__ X,
                             __nv_bfloat16* __restrict__ H,
                             __nv_bfloat16* __restrict__ L) {
    size_t i = (size_t)blockIdx.x * 256 + threadIdx.x;
    float v = X[i];
    __nv_bfloat16 h = __float2bfloat16(v);
    H[i] = h;
    L[i] = __float2bfloat16(v - __bfloat162float(h));
}

// W [L][K][N] fp32 -> T [L][N][K] bf16 hi/lo.  grid (N/32, K/32, L), block (32,8)
__global__ void wtrans_split_kernel(const float* __restrict__ W,
                                    __nv_bfloat16* __restrict__ Th,
                                    __nv_bfloat16* __restrict__ Tl,
                                    int K, int N) {
    __shared__ float t[32][33];
    const float* Wl = W + (size_t)blockIdx.z * K * N;
    size_t ob = (size_t)blockIdx.z * K * N;
    int x = blockIdx.x * 32 + threadIdx.x;   // N
    int y = blockIdx.y * 32 + threadIdx.y;   // K
#pragma unroll
    for (int j = 0; j < 32; j += 8)
        t[threadIdx.y + j][threadIdx.x] = Wl[(size_t)(y + j) * N + x];
    __syncthreads();
    int n = blockIdx.x * 32 + threadIdx.y;
    int k = blockIdx.y * 32 + threadIdx.x;
#pragma unroll
    for (int j = 0; j < 32; j += 8) {
        float v = t[threadIdx.x][threadIdx.y + j];
        __nv_bfloat16 h = __float2bfloat16(v);
        size_t o = ob + (size_t)(n + j) * K + k;
        Th[o] = h;
        Tl[o] = __float2bfloat16(v - __bfloat162float(h));
    }
}

// ---------------------------------------------------------------------------
// Patch extraction with split
// ---------------------------------------------------------------------------
__global__ void extract_patches_kernel(const float* __restrict__ img,
                                       __nv_bfloat16* __restrict__ H,
                                       __nv_bfloat16* __restrict__ L) {
    int idx = blockIdx.x * 256 + threadIdx.x;
    int col = idx % PATCHDIM;
    int row = idx / PATCHDIM;
    int b = row >> 7, t = row & 127;
    int h = t >> 4, w = t & 15;
    int c = col >> 10, r = col & 1023;
    int p = r >> 5, q = r & 31;
    float v = img[(((size_t)b * 3 + c) * 256 + h * 32 + p) * 512 + w * 32 + q];
    __nv_bfloat16 hh = __float2bfloat16(v);
    H[idx] = hh;
    L[idx] = __float2bfloat16(v - __bfloat162float(hh));
}

// ---------------------------------------------------------------------------
// LayerNorm
// ---------------------------------------------------------------------------
__device__ __forceinline__ void ln_stats(const float* __restrict__ x, size_t base,
                                         int D, float& mu, float& rstd) {
    float s = 0.f, ss = 0.f;
    for (int i = threadIdx.x; i < D; i += 256) {
        float v = x[base + i];
        s += v; ss += v * v;
    }
#pragma unroll
    for (int o = 16; o; o >>= 1) {
        s  += __shfl_xor_sync(0xffffffffu, s, o);
        ss += __shfl_xor_sync(0xffffffffu, ss, o);
    }
    __shared__ float sh[2][8];
    int w = threadIdx.x >> 5;
    if ((threadIdx.x & 31) == 0) { sh[0][w] = s; sh[1][w] = ss; }
    __syncthreads();
    if (threadIdx.x < 32) {
        s  = (threadIdx.x < 8) ? sh[0][threadIdx.x] : 0.f;
        ss = (threadIdx.x < 8) ? sh[1][threadIdx.x] : 0.f;
#pragma unroll
        for (int o = 4; o; o >>= 1) {
            s  += __shfl_xor_sync(0xffffffffu, s, o);
            ss += __shfl_xor_sync(0xffffffffu, ss, o);
        }
        if (threadIdx.x == 0) { sh[0][0] = s; sh[1][0] = ss; }
    }
    __syncthreads();
    s = sh[0][0]; ss = sh[1][0];
    float invD = 1.0f / (float)D;
    mu = s * invD;
    float var = ss * invD - mu * mu;
    rstd = rsqrtf(var + LN_EPS);
}

__global__ void ln_kernel(const float* __restrict__ x, const float* __restrict__ g,
                          const float* __restrict__ beta, float* __restrict__ y, int D) {
    size_t base = (size_t)blockIdx.x * D;
    float mu, rstd;
    ln_stats(x, base, D, mu, rstd);
    for (int i = threadIdx.x; i < D; i += 256)
        y[base + i] = (x[base + i] - mu) * rstd * g[i] + beta[i];
}

__global__ void ln_split_kernel(const float* __restrict__ x, const float* __restrict__ g,
                                const float* __restrict__ beta,
                                __nv_bfloat16* __restrict__ H,
                                __nv_bfloat16* __restrict__ L, int D) {
    size_t base = (size_t)blockIdx.x * D;
    float mu, rstd;
    ln_stats(x, base, D, mu, rstd);
    for (int i = threadIdx.x; i < D; i += 256) {
        float v = (x[base + i] - mu) * rstd * g[i] + beta[i];
        __nv_bfloat16 h = __float2bfloat16(v);
        H[base + i] = h;
        L[base + i] = __float2bfloat16(v - __bfloat162float(h));
    }
}

// ---------------------------------------------------------------------------
// x[row][d] += sph_pos[row%128] @ pos_w + pos_b
// ---------------------------------------------------------------------------
__global__ void add_pos_kernel(float* __restrict__ x, const float* __restrict__ sph_pos,
                               const float* __restrict__ pos_w,
                               const float* __restrict__ pos_b) {
    int idx = blockIdx.x * 256 + threadIdx.x;
    int d = idx & 1023;
    int i = (idx >> 10) & 127;
    x[idx] += sph_pos[i * 2] * pos_w[d] + sph_pos[i * 2 + 1] * pos_w[1024 + d] + pos_b[d];
}

// ---------------------------------------------------------------------------
// W[b,h,i,j] = (q_i . k_j) * 0.125 * (1 + dist[i,j]).  One block per (b,h).
// ---------------------------------------------------------------------------
__global__ __launch_bounds__(256) void qk_kernel(const float* __restrict__ qkv,
                                                 const float* __restrict__ dist,
                                                 float* __restrict__ W) {
    int b = blockIdx.x >> 4, hh = blockIdx.x & 15;
    const float* qb = qkv + (size_t)b * NTOK * PATCHDIM + hh * DHEAD;
    const float* kb = qb + DIMV;
    __shared__ float Qs[16][128];
    __shared__ float Ks[16][128];
    int tid = threadIdx.x, ty = tid >> 4, tx = tid & 15;
    int rr = tid >> 2, cc = tid & 3;

    float acc[8][8];
#pragma unroll
    for (int i = 0; i < 8; i++)
#pragma unroll
        for (int j = 0; j < 8; j++) acc[i][j] = 0.f;

    for (int kc = 0; kc < DHEAD; kc += 16) {
#pragma unroll
        for (int it = 0; it < 2; it++) {
            int row = rr + it * 64;
            float4 a = *(const float4*)(qb + (size_t)row * PATCHDIM + kc + cc * 4);
            Qs[cc*4+0][row] = a.x; Qs[cc*4+1][row] = a.y;
            Qs[cc*4+2][row] = a.z; Qs[cc*4+3][row] = a.w;
            float4 k4 = *(const float4*)(kb + (size_t)row * PATCHDIM + kc + cc * 4);
            Ks[cc*4+0][row] = k4.x; Ks[cc*4+1][row] = k4.y;
            Ks[cc*4+2][row] = k4.z; Ks[cc*4+3][row] = k4.w;
        }
        __syncthreads();
#pragma unroll
        for (int kk = 0; kk < 16; kk++) {
            float av[8], bv[8];
            *(float4*)(av)     = *(const float4*)&Qs[kk][ty * 8];
            *(float4*)(av + 4) = *(const float4*)&Qs[kk][ty * 8 + 4];
            *(float4*)(bv)     = *(const float4*)&Ks[kk][tx * 8];
            *(float4*)(bv + 4) = *(const float4*)&Ks[kk][tx * 8 + 4];
#pragma unroll
            for (int i = 0; i < 8; i++)
#pragma unroll
                for (int j = 0; j < 8; j++) acc[i][j] += av[i] * bv[j];
        }
        __syncthreads();
    }

    size_t wbase = (size_t)blockIdx.x * (NTOK * NTOK);
#pragma unroll
    for (int i = 0; i < 8; i++) {
        int irow = ty * 8 + i;
#pragma unroll
        for (int j = 0; j < 8; j++) {
            int jcol = tx * 8 + j;
            W[wbase + irow * 128 + jcol] =
                acc[i][j] * 0.125f * (1.0f + dist[irow * 128 + jcol]);
        }
    }
}

// ---------------------------------------------------------------------------
// Cross-head standardize (ddof=1) + softmax over j. Block per (b,i). In-place.
// ---------------------------------------------------------------------------
__global__ __launch_bounds__(128) void std_softmax_kernel(float* __restrict__ W) {
    int b = blockIdx.x >> 7, i = blockIdx.x & 127;
    int j = threadIdx.x;
    __shared__ float sm[NHEADS][128];

    size_t base = (size_t)b * (NHEADS * NTOK * NTOK) + (size_t)i * 128 + j;
    float vals[NHEADS];
    float s = 0.f;
#pragma unroll
    for (int h = 0; h < NHEADS; h++) {
        float v = W[base + (size_t)h * (NTOK * NTOK)];
        vals[h] = v; s += v;
    }
    float mu = s * (1.0f / 16.0f);
    float d2 = 0.f;
#pragma unroll
    for (int h = 0; h < NHEADS; h++) {
        float d = vals[h] - mu;
        d2 += d * d;
    }
    float inv = rsqrtf(d2 * (1.0f / 15.0f));
#pragma unroll
    for (int h = 0; h < NHEADS; h++) sm[h][j] = (vals[h] - mu) * inv;
    __syncthreads();

    int warp = j >> 5, lane = j & 31;
#pragma unroll
    for (int r = 0; r < 4; r++) {
        int h = warp * 4 + r;
        float v0 = sm[h][lane], v1 = sm[h][lane + 32];
        float v2 = sm[h][lane + 64], v3 = sm[h][lane + 96];
        float m = fmaxf(fmaxf(v0, v1), fmaxf(v2, v3));
#pragma unroll
        for (int o = 16; o; o >>= 1) m = fmaxf(m, __shfl_xor_sync(0xffffffffu, m, o));
        float e0 = expf(v0 - m), e1 = expf(v1 - m);
        float e2 = expf(v2 - m), e3 = expf(v3 - m);
        float sum = e0 + e1 + e2 + e3;
#pragma unroll
        for (int o = 16; o; o >>= 1) sum += __shfl_xor_sync(0xffffffffu, sum, o);
        float rs = 1.0f / sum;
        size_t wb = (size_t)b * (NHEADS * NTOK * NTOK) + (size_t)h * (NTOK * NTOK)
                  + (size_t)i * 128;
        W[wb + lane]      = e0 * rs;
        W[wb + lane + 32] = e1 * rs;
        W[wb + lane + 64] = e2 * rs;
        W[wb + lane + 96] = e3 * rs;
    }
}

// ---------------------------------------------------------------------------
// O (split bf16) = attn @ v.  One block per (b,h).
// ---------------------------------------------------------------------------
__global__ __launch_bounds__(256) void av_kernel(const float* __restrict__ W,
                                                 const float* __restrict__ qkv,
                                                 __nv_bfloat16* __restrict__ Oh,
                                                 __nv_bfloat16* __restrict__ Ol) {
    int b = blockIdx.x >> 4, hh = blockIdx.x & 15;
    const float* attn = W + (size_t)blockIdx.x * (NTOK * NTOK);
    const float* vb = qkv + (size_t)b * NTOK * PATCHDIM + 2 * DIMV + hh * DHEAD;
    __shared__ float Ts[16][128];
    __shared__ float Vs[16][64];
    int tid = threadIdx.x, ty = tid >> 4, tx = tid & 15;
    int rr = tid >> 2, cc = tid & 3;

    float acc[8][4];
#pragma unroll
    for (int i = 0; i < 8; i++)
#pragma unroll
        for (int d = 0; d < 4; d++) acc[i][d] = 0.f;

    for (int jc = 0; jc < NTOK; jc += 16) {
#pragma unroll
        for (int it = 0; it < 2; it++) {
            int row = rr + it * 64;
            float4 a = *(const float4*)(attn + (size_t)row * 128 + jc + cc * 4);
            Ts[cc*4+0][row] = a.x; Ts[cc*4+1][row] = a.y;
            Ts[cc*4+2][row] = a.z; Ts[cc*4+3][row] = a.w;
        }
        {
            int jj = tid >> 4;
            int c4 = tid & 15;
            float4 v4 = *(const float4*)(vb + (size_t)(jc + jj) * PATCHDIM + c4 * 4);
            *(float4*)(&Vs[jj][c4 * 4]) = v4;
        }
        __syncthreads();
#pragma unroll
        for (int kk = 0; kk < 16; kk++) {
            float av8[8], vv[4];
            *(float4*)(av8)     = *(const float4*)&Ts[kk][ty * 8];
            *(float4*)(av8 + 4) = *(const float4*)&Ts[kk][ty * 8 + 4];
            *(float4*)(vv)      = *(const float4*)&Vs[kk][tx * 4];
#pragma unroll
            for (int i = 0; i < 8; i++)
#pragma unroll
                for (int d = 0; d < 4; d++) acc[i][d] += av8[i] * vv[d];
        }
        __syncthreads();
    }
#pragma unroll
    for (int i = 0; i < 8; i++) {
        int irow = ty * 8 + i;
        size_t ob = (size_t)(b * 128 + irow) * DIMV + hh * DHEAD + tx * 4;
#pragma unroll
        for (int d = 0; d < 4; d++) {
            float v = acc[i][d];
            __nv_bfloat16 h = __float2bfloat16(v);
            Oh[ob + d] = h;
            Ol[ob + d] = __float2bfloat16(v - __bfloat162float(h));
        }
    }
}

// ---------------------------------------------------------------------------
// Reassemble: out[b,c,h*32+p1,w*32+p2] = Y[b*128+h*16+w][(p1*32+p2)*3 + c]
// ---------------------------------------------------------------------------
__global__ void reassemble_kernel(const float* __restrict__ Y, float* __restrict__ out) {
    int idx = blockIdx.x * 256 + threadIdx.x;
    int xq = idx & 511;
    int rest = idx >> 9;
    int yr = rest & 255;
    rest >>= 8;
    int c = rest % 3;
    int b = rest / 3;
    int h = yr >> 5, p1 = yr & 31, w = xq >> 5, p2 = xq & 31;
    out[idx] = Y[(size_t)(b * 128 + h * 16 + w) * PATCHDIM + (p1 * 32 + p2) * 3 + c];
}

// ---------------------------------------------------------------------------
// Host launcher
// ---------------------------------------------------------------------------
extern "C" void kernel_launch(void* const* d_in, const int* in_sizes, int n_in,
                              void* d_out, int out_size)
{
    const float* img      = (const float*)d_in[0];
    const float* sph_pos  = (const float*)d_in[1];
    const float* sph_dist = (const float*)d_in[2];
    const float* conv_w   = (const float*)d_in[3];
    const float* conv_b   = (const float*)d_in[4];
    const float* nl_ln1_g = (const float*)d_in[5];
    const float* nl_ln1_b = (const float*)d_in[6];
    const float* nl_w     = (const float*)d_in[7];
    const float* nl_b     = (const float*)d_in[8];
    const float* nl_ln2_g = (const float*)d_in[9];
    const float* nl_ln2_b = (const float*)d_in[10];
    const float* pos_w    = (const float*)d_in[11];
    const float* pos_b    = (const float*)d_in[12];
    const float* ln_g     = (const float*)d_in[13];
    const float* ln_b     = (const float*)d_in[14];
    const float* wqkv     = (const float*)d_in[15];
    const float* wo       = (const float*)d_in[16];
    const float* wo_b     = (const float*)d_in[17];
    const float* tr_ln_g  = (const float*)d_in[18];
    const float* tr_ln_b  = (const float*)d_in[19];
    const float* exp_w    = (const float*)d_in[20];
    const float* exp_b    = (const float*)d_in[21];
    const float* out_ln_g = (const float*)d_in[22];
    const float* out_ln_b = (const float*)d_in[23];

    float *big, *qkv, *x, *w;
    cudaGetSymbolAddress((void**)&big, g_big);
    cudaGetSymbolAddress((void**)&qkv, g_qkv);
    cudaGetSymbolAddress((void**)&x,   g_x);
    cudaGetSymbolAddress((void**)&w,   g_w);
    __nv_bfloat16 *Xph, *Xpl, *hh, *hl, *oh, *ol;
    __nv_bfloat16 *cwh, *cwl, *nlwh, *nlwl, *qwh, *qwl, *owh, *owl, *ewh, *ewl;
    cudaGetSymbolAddress((void**)&Xph, g_Xph);  cudaGetSymbolAddress((void**)&Xpl, g_Xpl);
    cudaGetSymbolAddress((void**)&hh,  g_hh);   cudaGetSymbolAddress((void**)&hl,  g_hl);
    cudaGetSymbolAddress((void**)&oh,  g_oh);   cudaGetSymbolAddress((void**)&ol,  g_ol);
    cudaGetSymbolAddress((void**)&cwh, g_cwh);  cudaGetSymbolAddress((void**)&cwl, g_cwl);
    cudaGetSymbolAddress((void**)&nlwh,g_nlwh); cudaGetSymbolAddress((void**)&nlwl,g_nlwl);
    cudaGetSymbolAddress((void**)&qwh, g_qwh);  cudaGetSymbolAddress((void**)&qwl, g_qwl);
    cudaGetSymbolAddress((void**)&owh, g_owh);  cudaGetSymbolAddress((void**)&owl, g_owl);
    cudaGetSymbolAddress((void**)&ewh, g_ewh);  cudaGetSymbolAddress((void**)&ewl, g_ewl);

    cudaFuncSetAttribute(hmma_gemm_kernel,
                         cudaFuncAttributeMaxDynamicSharedMemorySize, HG_SMEM);

    // ---- weight prep (bf16 hi/lo, transposed to [N,K]) ----
    split_kernel<<<DIMV * PATCHDIM / 256, 256>>>(conv_w, cwh, cwl);   // already [N,K]
    wtrans_split_kernel<<<dim3(DIMV/32, DIMV/32, 1),     dim3(32,8)>>>(nl_w,  nlwh, nlwl, DIMV, DIMV);
    wtrans_split_kernel<<<dim3(PATCHDIM/32, DIMV/32, DEPTH), dim3(32,8)>>>(wqkv, qwh, qwl, DIMV, PATCHDIM);
    wtrans_split_kernel<<<dim3(DIMV/32, DIMV/32, DEPTH), dim3(32,8)>>>(wo,    owh,  owl,  DIMV, DIMV);
    wtrans_split_kernel<<<dim3(PATCHDIM/32, DIMV/32, 1), dim3(32,8)>>>(exp_w, ewh,  ewl,  DIMV, PATCHDIM);

    // ---- patch embedding ----
    extract_patches_kernel<<<ROWS * PATCHDIM / 256, 256>>>(img, Xph, Xpl);
    hmma_gemm_kernel<<<dim3(DIMV/128, ROWS/128), 256, HG_SMEM>>>(
        Xph, Xpl, cwh, cwl, conv_b, nullptr, x, ROWS, DIMV, PATCHDIM);

    // ---- norm_linear + positional embedding ----
    ln_split_kernel<<<ROWS, 256>>>(x, nl_ln1_g, nl_ln1_b, hh, hl, DIMV);
    hmma_gemm_kernel<<<dim3(DIMV/128, ROWS/128), 256, HG_SMEM>>>(
        hh, hl, nlwh, nlwl, nl_b, nullptr, x, ROWS, DIMV, DIMV);
    ln_kernel<<<ROWS, 256>>>(x, nl_ln2_g, nl_ln2_b, x, DIMV);
    add_pos_kernel<<<ROWS * DIMV / 256, 256>>>(x, sph_pos, pos_w, pos_b);

    // ---- transformer layers ----
    for (int l = 0; l < DEPTH; l++) {
        ln_split_kernel<<<ROWS, 256>>>(x, ln_g + l * DIMV, ln_b + l * DIMV, hh, hl, DIMV);
        hmma_gemm_kernel<<<dim3(PATCHDIM/128, ROWS/128), 256, HG_SMEM>>>(
            hh, hl, qwh + (size_t)l * PATCHDIM * DIMV, qwl + (size_t)l * PATCHDIM * DIMV,
            nullptr, nullptr, qkv, ROWS, PATCHDIM, DIMV);
        qk_kernel<<<BATCH * NHEADS, 256>>>(qkv, sph_dist, w);
        std_softmax_kernel<<<BATCH * NTOK, 128>>>(w);
        av_kernel<<<BATCH * NHEADS, 256>>>(w, qkv, oh, ol);
        hmma_gemm_kernel<<<dim3(DIMV/128, ROWS/128), 256, HG_SMEM>>>(
            oh, ol, owh + (size_t)l * DIMV * DIMV, owl + (size_t)l * DIMV * DIMV,
            wo_b + l * DIMV, x, x, ROWS, DIMV, DIMV);
    }

    // ---- final LN + expand + output LN + reassembly ----
    ln_split_kernel<<<ROWS, 256>>>(x, tr_ln_g, tr_ln_b, hh, hl, DIMV);
    hmma_gemm_kernel<<<dim3(PATCHDIM/128, ROWS/128), 256, HG_SMEM>>>(
        hh, hl, ewh, ewl, exp_b, nullptr, big, ROWS, PATCHDIM, DIMV);
    ln_kernel<<<ROWS, 256>>>(big, out_ln_g, out_ln_b, big, PATCHDIM);
    reassemble_kernel<<<ROWS * PATCHDIM / 256, 256>>>(big, (float*)d_out);
}